// round 1
// baseline (speedup 1.0000x reference)
#include <cuda_runtime.h>

// Outputs concatenated (row-major, fp32):
//   [ 0,16)  x3 = a @ b.T        [4,4]
//   [16,32)  x4 = x3.T           [4,4]
//   [32,40)  v1 = a              [4,2]
//   [40,48)  v2 = a.T            [2,4]
//   [48,52)  v3 = a.T @ a        [2,2]
//   [52,68)  v4 = a @ a.T        [4,4]
//   [68,72)  v5 = b.T @ a        [2,2]
//   [72,88)  v6 = a @ b.T        [4,4]  (== x3)
//   [88,96)  v7 = a.T            [2,4]  (== v2)
// where a = x1.reshape(4,2), b = x2.reshape(4,2), both row-major flat.

__global__ void model_kernel(const float* __restrict__ x1,
                             const float* __restrict__ x2,
                             float* __restrict__ out) {
    const int o = threadIdx.x;
    if (o >= 96) return;

    // a[i][k] = x1[i*2+k], b[i][k] = x2[i*2+k]
    float r;
    if (o < 16) {                       // x3[i][j] = sum_k a[i][k]*b[j][k]
        int i = o >> 2, j = o & 3;
        r = x1[i*2+0]*x2[j*2+0] + x1[i*2+1]*x2[j*2+1];
    } else if (o < 32) {                // x4[i][j] = x3[j][i]
        int t = o - 16, i = t >> 2, j = t & 3;
        r = x1[j*2+0]*x2[i*2+0] + x1[j*2+1]*x2[i*2+1];
    } else if (o < 40) {                // v1 flat == x1 flat
        r = x1[o - 32];
    } else if (o < 48) {                // v2[i][j] = a[j][i]
        int t = o - 40, i = t >> 2, j = t & 3;
        r = x1[j*2+i];
    } else if (o < 52) {                // v3[i][j] = sum_k a[k][i]*a[k][j]
        int t = o - 48, i = t >> 1, j = t & 1;
        r = x1[0*2+i]*x1[0*2+j] + x1[1*2+i]*x1[1*2+j]
          + x1[2*2+i]*x1[2*2+j] + x1[3*2+i]*x1[3*2+j];
    } else if (o < 68) {                // v4[i][j] = sum_k a[i][k]*a[j][k]
        int t = o - 52, i = t >> 2, j = t & 3;
        r = x1[i*2+0]*x1[j*2+0] + x1[i*2+1]*x1[j*2+1];
    } else if (o < 72) {                // v5[i][j] = sum_k b[k][i]*a[k][j]
        int t = o - 68, i = t >> 1, j = t & 1;
        r = x2[0*2+i]*x1[0*2+j] + x2[1*2+i]*x1[1*2+j]
          + x2[2*2+i]*x1[2*2+j] + x2[3*2+i]*x1[3*2+j];
    } else if (o < 88) {                // v6 == x3
        int t = o - 72, i = t >> 2, j = t & 3;
        r = x1[i*2+0]*x2[j*2+0] + x1[i*2+1]*x2[j*2+1];
    } else {                            // v7 == v2
        int t = o - 88, i = t >> 2, j = t & 3;
        r = x1[j*2+i];
    }
    out[o] = r;
}

extern "C" void kernel_launch(void* const* d_in, const int* in_sizes, int n_in,
                              void* d_out, int out_size) {
    const float* x1 = (const float*)d_in[0];
    const float* x2 = (const float*)d_in[1];
    float* out = (float*)d_out;
    model_kernel<<<1, 96>>>(x1, x2, out);
}